// round 6
// baseline (speedup 1.0000x reference)
#include <cuda_runtime.h>
#include <cuda_bf16.h>

// IoUMetricLoss: pred_label fp32 [8,19,512,1024], label int32 [8,512,1024]
// out: scalar fp32 = 1 - nanmean(IoU per class), all-NaN -> 0.5
//
// R6: R5 structure (4 px/thread, 4096x256, fused last-block finalize) +
// warp-aggregated histogram atomics via __match_any_sync. R3/R5 showed the
// smem-atomic lane traffic (2 full-warp atomics per pixel) co-binding with
// DRAM at ~72%; aggregation cuts atomic lane-ops ~2x (32+32 -> ~16+16 per
// 4-pixel slot) and moves the per-group counting onto idle ALU pipes.

#define NUM_CLASSES 19
#define HW_SHIFT 19                  // 512*1024 = 2^19
#define HW (1 << HW_SHIFT)
#define BATCH 8
#define TOTAL_PIX (BATCH * HW)       // 4194304
#define VEC_GROUPS (TOTAL_PIX / 4)   // 1048576
#define HIST_BLOCK 256
#define WARPS_PER_BLOCK (HIST_BLOCK / 32)
#define GRID_BLOCKS (VEC_GROUPS / HIST_BLOCK)   // 4096

// Global accumulators (no cudaMalloc allowed). Statically zero; the
// finalizing block re-zeros them so every graph replay sees clean state.
// g_li[c]: low 32 = area_label, high 32 = area_intersect.
__device__ unsigned long long g_li[NUM_CLASSES];
__device__ unsigned int       g_pred[NUM_CLASSES];
__device__ unsigned int       g_done;

__device__ __forceinline__ void amax_step(float v, float& bv, int& bi, int c) {
    float m = fmaxf(bv, v);
    bi = (v > bv) ? c : bi;
    bv = m;
}

// Warp-aggregated histogram update for one pixel slot.
// l: label, i: argmax index, lane: lane id, warp-private smem hists.
__device__ __forceinline__ void acc_slot(
    int l, int i, int lane,
    unsigned long long* __restrict__ li_hist,
    unsigned int* __restrict__ pr_hist)
{
    const unsigned full  = 0xFFFFFFFFu;
    const unsigned valid = __ballot_sync(full, l >= 0);

    // label + intersect, packed into one 64-bit atomic per distinct label
    unsigned mlab  = __match_any_sync(full, l) & valid;
    unsigned inter = __ballot_sync(full, i == l);
    if (l >= 0 && lane == (__ffs(mlab) - 1)) {
        unsigned cnt  = __popc(mlab);
        unsigned icnt = __popc(mlab & inter);
        atomicAdd(&li_hist[l],
                  (unsigned long long)cnt | ((unsigned long long)icnt << 32));
    }

    // pred count, one 32-bit atomic per distinct predicted class
    unsigned mpred = __match_any_sync(full, i) & valid;
    if (l >= 0 && lane == (__ffs(mpred) - 1)) {
        atomicAdd(&pr_hist[i], __popc(mpred));
    }
}

__global__ void __launch_bounds__(HIST_BLOCK)
iou_fused_kernel(const float* __restrict__ pred,
                 const int* __restrict__ label,
                 float* __restrict__ out) {
    __shared__ unsigned long long s_li[WARPS_PER_BLOCK][NUM_CLASSES];
    __shared__ unsigned int       s_pr[WARPS_PER_BLOCK][NUM_CLASSES];
    __shared__ int                s_is_last;

    const int warp = threadIdx.x >> 5;
    const int lane = threadIdx.x & 31;

    if (lane < NUM_CLASSES) {
        s_li[warp][lane] = 0ULL;
        s_pr[warp][lane] = 0u;
    }
    __syncwarp();

    const unsigned t  = blockIdx.x * blockDim.x + threadIdx.x;  // 0..VEC_GROUPS-1
    const unsigned P  = t << 2;                 // first of 4 consecutive pixels
    const unsigned b  = P >> HW_SHIFT;          // batch index
    const unsigned hw = P & (HW - 1);

    const float* base = pred + ((size_t)b * NUM_CLASSES << HW_SHIFT) + hw;

    // label first — independent stream
    int4 lv = __ldcs((const int4*)(label + P));

    // argmax over 19 classes for 4 pixels
    float4 bv = __ldcs((const float4*)base);
    int i0 = 0, i1 = 0, i2 = 0, i3 = 0;
    #pragma unroll
    for (int c = 1; c < NUM_CLASSES; c++) {
        float4 v = __ldcs((const float4*)(base + ((size_t)c << HW_SHIFT)));
        amax_step(v.x, bv.x, i0, c);
        amax_step(v.y, bv.y, i1, c);
        amax_step(v.z, bv.z, i2, c);
        amax_step(v.w, bv.w, i3, c);
    }

    // warp-aggregated accumulation, one slot at a time
    acc_slot(lv.x, i0, lane, s_li[warp], s_pr[warp]);
    acc_slot(lv.y, i1, lane, s_li[warp], s_pr[warp]);
    acc_slot(lv.z, i2, lane, s_li[warp], s_pr[warp]);
    acc_slot(lv.w, i3, lane, s_li[warp], s_pr[warp]);

    __syncthreads();

    // block reduce: one global atomic per class per counter
    if (threadIdx.x < NUM_CLASSES) {
        unsigned long long li = 0ULL;
        unsigned int       pr = 0u;
        #pragma unroll
        for (int w2 = 0; w2 < WARPS_PER_BLOCK; w2++) {
            li += s_li[w2][threadIdx.x];
            pr += s_pr[w2][threadIdx.x];
        }
        atomicAdd(&g_li[threadIdx.x], li);
        atomicAdd(&g_pred[threadIdx.x], pr);
    }
    __syncthreads();

    // last-block-done finalize + state reset
    if (threadIdx.x == 0) {
        __threadfence();
        unsigned prev = atomicAdd(&g_done, 1u);
        s_is_last = (prev == gridDim.x - 1);
    }
    __syncthreads();
    if (!s_is_last) return;

    if (threadIdx.x < 32) {
        const int c = threadIdx.x;
        float iou_sum = 0.0f;
        int   valid   = 0;
        if (c < NUM_CLASSES) {
            unsigned long long li = g_li[c];
            unsigned int pr    = g_pred[c];
            unsigned int lab   = (unsigned int)(li & 0xFFFFFFFFULL);
            unsigned int inter = (unsigned int)(li >> 32);
            unsigned long long uni =
                (unsigned long long)lab + (unsigned long long)pr
                - (unsigned long long)inter;
            if (uni > 0ULL) {
                iou_sum = (float)inter / (float)uni;
                valid   = 1;
            }
            // uni == 0 -> 0/0 = NaN in reference, excluded by nanmean
            g_li[c]   = 0ULL;   // reset for next graph replay
            g_pred[c] = 0u;
        }
        #pragma unroll
        for (int o = 16; o > 0; o >>= 1) {
            iou_sum += __shfl_down_sync(0xFFFFFFFFu, iou_sum, o);
            valid   += __shfl_down_sync(0xFFFFFFFFu, valid, o);
        }
        if (c == 0) {
            g_done = 0u;
            float loss = (valid > 0) ? (1.0f - iou_sum / (float)valid) : 0.5f;
            *out = loss;
        }
    }
}

extern "C" void kernel_launch(void* const* d_in, const int* in_sizes, int n_in,
                              void* d_out, int out_size) {
    // pred = 79,691,776 elems; label = 4,194,304 (resolve by size).
    const float* pred;
    const int*   label;
    if (in_sizes[0] >= in_sizes[1]) {
        pred  = (const float*)d_in[0];
        label = (const int*)d_in[1];
    } else {
        pred  = (const float*)d_in[1];
        label = (const int*)d_in[0];
    }
    float* out = (float*)d_out;

    iou_fused_kernel<<<GRID_BLOCKS, HIST_BLOCK>>>(pred, label, out);
}

// round 7
// speedup vs baseline: 1.1162x; 1.1162x over previous
#include <cuda_runtime.h>
#include <cuda_bf16.h>

// IoUMetricLoss: pred_label fp32 [8,19,512,1024], label int32 [8,512,1024]
// out: scalar fp32 = 1 - nanmean(IoU per class), all-NaN -> 0.5
//
// R7: R3/R5 proven body (4 px/thread, per-pixel packed smem atomics), but
// block=128 / grid=8192. regs=38 x 128 threads -> 13 CTAs/SM -> occ ~81%
// (vs 70% at block=256), raising outstanding load bytes per SM ~16% to
// attack the DRAM=72% exposed-latency plateau. R6's warp-aggregation is
// reverted (it cut atomic traffic and REGRESSED -> atomics not binding).

#define NUM_CLASSES 19
#define HW_SHIFT 19                  // 512*1024 = 2^19
#define HW (1 << HW_SHIFT)
#define BATCH 8
#define TOTAL_PIX (BATCH * HW)       // 4194304
#define VEC_GROUPS (TOTAL_PIX / 4)   // 1048576
#define HIST_BLOCK 128
#define WARPS_PER_BLOCK (HIST_BLOCK / 32)
#define GRID_BLOCKS (VEC_GROUPS / HIST_BLOCK)   // 8192

// Global accumulators (no cudaMalloc allowed). Statically zero; the
// finalizing block re-zeros them so every graph replay sees clean state.
// g_li[c]: low 32 = area_label, high 32 = area_intersect.
__device__ unsigned long long g_li[NUM_CLASSES];
__device__ unsigned int       g_pred[NUM_CLASSES];
__device__ unsigned int       g_done;

__device__ __forceinline__ void amax_step(float v, float& bv, int& bi, int c) {
    float m = fmaxf(bv, v);
    bi = (v > bv) ? c : bi;
    bv = m;
}

__global__ void __launch_bounds__(HIST_BLOCK)
iou_fused_kernel(const float* __restrict__ pred,
                 const int* __restrict__ label,
                 float* __restrict__ out) {
    __shared__ unsigned long long s_li[WARPS_PER_BLOCK][NUM_CLASSES];
    __shared__ unsigned int       s_pr[WARPS_PER_BLOCK][NUM_CLASSES];
    __shared__ int                s_is_last;

    const int warp = threadIdx.x >> 5;
    const int lane = threadIdx.x & 31;

    if (lane < NUM_CLASSES) {
        s_li[warp][lane] = 0ULL;
        s_pr[warp][lane] = 0u;
    }
    __syncwarp();

    const unsigned t  = blockIdx.x * blockDim.x + threadIdx.x;  // 0..VEC_GROUPS-1
    const unsigned P  = t << 2;                 // first of 4 consecutive pixels
    const unsigned b  = P >> HW_SHIFT;          // batch index
    const unsigned hw = P & (HW - 1);

    const float* base = pred + ((size_t)b * NUM_CLASSES << HW_SHIFT) + hw;

    // label first — independent stream
    int4 lv = __ldcs((const int4*)(label + P));

    // argmax over 19 classes for 4 pixels
    float4 bv = __ldcs((const float4*)base);
    int i0 = 0, i1 = 0, i2 = 0, i3 = 0;
    #pragma unroll
    for (int c = 1; c < NUM_CLASSES; c++) {
        float4 v = __ldcs((const float4*)(base + ((size_t)c << HW_SHIFT)));
        amax_step(v.x, bv.x, i0, c);
        amax_step(v.y, bv.y, i1, c);
        amax_step(v.z, bv.z, i2, c);
        amax_step(v.w, bv.w, i3, c);
    }

    // accumulate: packed label(+intersect) atomic + pred atomic, per pixel
    #define ACC(l, i)                                                          \
        if ((l) >= 0) {                                                        \
            atomicAdd(&s_li[warp][(l)],                                        \
                      1ULL | (((i) == (l)) ? (1ULL << 32) : 0ULL));            \
            atomicAdd(&s_pr[warp][(i)], 1u);                                   \
        }
    ACC(lv.x, i0); ACC(lv.y, i1); ACC(lv.z, i2); ACC(lv.w, i3);
    #undef ACC

    __syncthreads();

    // block reduce: one global atomic per class per counter
    if (threadIdx.x < NUM_CLASSES) {
        unsigned long long li = 0ULL;
        unsigned int       pr = 0u;
        #pragma unroll
        for (int w2 = 0; w2 < WARPS_PER_BLOCK; w2++) {
            li += s_li[w2][threadIdx.x];
            pr += s_pr[w2][threadIdx.x];
        }
        atomicAdd(&g_li[threadIdx.x], li);
        atomicAdd(&g_pred[threadIdx.x], pr);
    }
    __syncthreads();

    // last-block-done finalize + state reset
    if (threadIdx.x == 0) {
        __threadfence();
        unsigned prev = atomicAdd(&g_done, 1u);
        s_is_last = (prev == gridDim.x - 1);
    }
    __syncthreads();
    if (!s_is_last) return;

    if (threadIdx.x < 32) {
        const int c = threadIdx.x;
        float iou_sum = 0.0f;
        int   valid   = 0;
        if (c < NUM_CLASSES) {
            unsigned long long li = g_li[c];
            unsigned int pr    = g_pred[c];
            unsigned int lab   = (unsigned int)(li & 0xFFFFFFFFULL);
            unsigned int inter = (unsigned int)(li >> 32);
            unsigned long long uni =
                (unsigned long long)lab + (unsigned long long)pr
                - (unsigned long long)inter;
            if (uni > 0ULL) {
                iou_sum = (float)inter / (float)uni;
                valid   = 1;
            }
            // uni == 0 -> 0/0 = NaN in reference, excluded by nanmean
            g_li[c]   = 0ULL;   // reset for next graph replay
            g_pred[c] = 0u;
        }
        #pragma unroll
        for (int o = 16; o > 0; o >>= 1) {
            iou_sum += __shfl_down_sync(0xFFFFFFFFu, iou_sum, o);
            valid   += __shfl_down_sync(0xFFFFFFFFu, valid, o);
        }
        if (c == 0) {
            g_done = 0u;
            float loss = (valid > 0) ? (1.0f - iou_sum / (float)valid) : 0.5f;
            *out = loss;
        }
    }
}

extern "C" void kernel_launch(void* const* d_in, const int* in_sizes, int n_in,
                              void* d_out, int out_size) {
    // pred = 79,691,776 elems; label = 4,194,304 (resolve by size).
    const float* pred;
    const int*   label;
    if (in_sizes[0] >= in_sizes[1]) {
        pred  = (const float*)d_in[0];
        label = (const int*)d_in[1];
    } else {
        pred  = (const float*)d_in[1];
        label = (const int*)d_in[0];
    }
    float* out = (float*)d_out;

    iou_fused_kernel<<<GRID_BLOCKS, HIST_BLOCK>>>(pred, label, out);
}